// round 3
// baseline (speedup 1.0000x reference)
#include <cuda_runtime.h>
#include <cstdint>

// Ragged (values, offsets[int32], dimension) -> dense [num_rows, 32] float32.
// NOTE: reference is JAX without x64 -> offsets buffer is int32, not int64.
// Row i spans values[offsets[i] : offsets[i+1]) (last row ends at total).
// Columns within a row are unique -> plain masked copy, no atomics needed.
// 8 threads per row, each thread writes one float4 (4 columns) -> 128B/row
// fully-coalesced stores; every output element written exactly once.

__global__ void ragged_to_dense_32(const float* __restrict__ values,
                                   const int* __restrict__ offsets,
                                   float4* __restrict__ out,
                                   int num_rows,
                                   int total_vals) {
    int gid = blockIdx.x * blockDim.x + threadIdx.x;   // one float4 per thread
    int row = gid >> 3;            // 8 threads per row (32 cols / 4)
    int sub = gid & 7;
    if (row >= num_rows) return;

    int start = __ldg(&offsets[row]);
    int end   = (row + 1 < num_rows) ? __ldg(&offsets[row + 1]) : total_vals;
    int len = end - start;

    int c0 = sub << 2;             // first column handled by this thread
    const float* src = values + start + c0;

    float4 v;
    v.x = (c0 + 0 < len) ? __ldg(src + 0) : 0.0f;
    v.y = (c0 + 1 < len) ? __ldg(src + 1) : 0.0f;
    v.z = (c0 + 2 < len) ? __ldg(src + 2) : 0.0f;
    v.w = (c0 + 3 < len) ? __ldg(src + 3) : 0.0f;

    out[gid] = v;                  // coalesced: 8 float4 = 128B per row
}

// Generic fallback for dim != 32 (not expected for this problem's shapes).
__global__ void ragged_to_dense_generic(const float* __restrict__ values,
                                        const int* __restrict__ offsets,
                                        float* __restrict__ out,
                                        int num_rows, int dim,
                                        int total_vals) {
    long long gid = (long long)blockIdx.x * blockDim.x + threadIdx.x;
    long long n = (long long)num_rows * dim;
    if (gid >= n) return;
    int row = (int)(gid / dim);
    int col = (int)(gid - (long long)row * dim);
    int start = offsets[row];
    int end   = (row + 1 < num_rows) ? offsets[row + 1] : total_vals;
    int len = end - start;
    out[gid] = (col < len) ? values[start + col] : 0.0f;
}

extern "C" void kernel_launch(void* const* d_in, const int* in_sizes, int n_in,
                              void* d_out, int out_size) {
    const float* values  = (const float*)d_in[0];
    const int*   offsets = (const int*)d_in[1];
    // d_in[2] = dimension scalar (int32); derive dim host-side from sizes.
    int num_rows   = in_sizes[1];
    int total_vals = in_sizes[0];
    int dim        = out_size / num_rows;

    if (dim == 32) {
        int threads_total = num_rows * 8;            // 8 float4-threads per row
        int block = 256;
        int grid = (threads_total + block - 1) / block;
        ragged_to_dense_32<<<grid, block>>>(values, offsets, (float4*)d_out,
                                            num_rows, total_vals);
    } else {
        long long n = (long long)num_rows * dim;
        int block = 256;
        long long grid = (n + block - 1) / block;
        ragged_to_dense_generic<<<(int)grid, block>>>(values, offsets, (float*)d_out,
                                                      num_rows, dim, total_vals);
    }
}

// round 11
// speedup vs baseline: 1.1610x; 1.1610x over previous
#include <cuda_runtime.h>
#include <cstdint>

// Ragged (values, offsets[int32], dimension) -> dense [num_rows, 32] float32.
// Block-staged, alignment-free variant: each 256-thread block handles 128 rows.
//   1. offsets[row0 .. row0+128] -> smem (coalesced)
//   2. values[base .. limit) -> smem via SCALAR coalesced loads (lanes are
//      consecutive -> 1 wavefront per 128B line, same sectors as LDG.128)
//   3. gather from smem per (row, col-quad), fully coalesced float4 stores
//      (STG.128 to d_out proved safe by the R3 passing kernel)
// No 128-bit shared or global LOADS anywhere -> no alignment hazards.

#define RPB      128                 // rows per block
#define NTHREADS 256
#define SVAL     (RPB * 32 + 32)     // span + gather-overrun slack

__global__ __launch_bounds__(NTHREADS)
void ragged_to_dense_32(const float* __restrict__ values,
                        const int* __restrict__ offsets,
                        float4* __restrict__ out,
                        int num_rows, int total_vals) {
    __shared__ float s_val[SVAL];
    __shared__ int   s_off[RPB + 1];

    const int tid  = threadIdx.x;
    const int row0 = blockIdx.x * RPB;

    // 1. offsets into smem (coalesced, 129 ints)
    if (tid <= RPB) {
        int r = row0 + tid;
        s_off[tid] = (r < num_rows) ? __ldg(&offsets[r]) : total_vals;
    }
    __syncthreads();

    const int base  = s_off[0];
    const int limit = s_off[RPB];
    int span = limit - base;
    if (span < 0) span = 0;
    if (span > SVAL) span = SVAL;                    // defensive smem cap

    // 2. scalar coalesced copy of the block's values span into smem
    for (int i = tid; i < span; i += NTHREADS) {
        int g = base + i;
        s_val[i] = (g < total_vals) ? __ldg(&values[g]) : 0.0f;
    }
    __syncthreads();

    // 3. gather + coalesced stores: 4 tasks/thread, task = (local row, col quad)
    const int out_base = row0 * 8;                   // float4 units (32 cols = 8 f4)
    #pragma unroll
    for (int k = 0; k < 4; k++) {
        int task = tid + k * NTHREADS;               // 0 .. 1023
        int rl   = task >> 3;                        // local row
        int sub  = task & 7;                         // col quad
        int st   = s_off[rl];
        int len  = s_off[rl + 1] - st;
        int c0   = sub << 2;
        int si   = (st - base) + c0;                 // smem gather index
        si = (si < 0) ? 0 : ((si > SVAL - 4) ? (SVAL - 4) : si);  // defensive

        float4 v;                                    // scalar LDS, no alignment req
        v.x = (c0 + 0 < len) ? s_val[si + 0] : 0.0f;
        v.y = (c0 + 1 < len) ? s_val[si + 1] : 0.0f;
        v.z = (c0 + 2 < len) ? s_val[si + 2] : 0.0f;
        v.w = (c0 + 3 < len) ? s_val[si + 3] : 0.0f;

        out[out_base + task] = v;                    // warp: 512B contiguous STG.128
    }
}

// Generic fallback for dim != 32 (not expected for this problem's shapes).
__global__ void ragged_to_dense_generic(const float* __restrict__ values,
                                        const int* __restrict__ offsets,
                                        float* __restrict__ out,
                                        int num_rows, int dim,
                                        int total_vals) {
    long long gid = (long long)blockIdx.x * blockDim.x + threadIdx.x;
    long long n = (long long)num_rows * dim;
    if (gid >= n) return;
    int row = (int)(gid / dim);
    int col = (int)(gid - (long long)row * dim);
    int start = offsets[row];
    int end   = (row + 1 < num_rows) ? offsets[row + 1] : total_vals;
    int len = end - start;
    out[gid] = (col < len) ? values[start + col] : 0.0f;
}

extern "C" void kernel_launch(void* const* d_in, const int* in_sizes, int n_in,
                              void* d_out, int out_size) {
    const float* values  = (const float*)d_in[0];
    const int*   offsets = (const int*)d_in[1];
    int num_rows   = in_sizes[1];
    int total_vals = in_sizes[0];
    int dim        = out_size / num_rows;

    if (dim == 32 && (((uintptr_t)d_out & 15) == 0)) {
        int grid = (num_rows + RPB - 1) / RPB;
        ragged_to_dense_32<<<grid, NTHREADS>>>(values, offsets, (float4*)d_out,
                                               num_rows, total_vals);
    } else {
        long long n = (long long)num_rows * dim;
        int block = 256;
        long long grid = (n + block - 1) / block;
        ragged_to_dense_generic<<<(int)grid, block>>>(values, offsets, (float*)d_out,
                                                      num_rows, dim, total_vals);
    }
}